// round 2
// baseline (speedup 1.0000x reference)
#include <cuda_runtime.h>
#include <math.h>

// Problem constants
#define BB   8
#define SEQL 4096
#define QL   1024
#define CIN  256
#define KVD  640
#define QD   128
#define HH   8
#define KD   16
#define VD   64
#define COUT 512
#define EPSB 1e-3f

// Intermediates as __device__ globals (no dynamic allocation allowed)
__device__ float d_kvbuf[BB * SEQL * KVD];   // [B, SEQ, 640]  (BN folded)
__device__ float d_qbuf [BB * QL * QD];      // [B, QLEN, 128] (BN folded)
__device__ float d_zbuf [BB * QL * COUT];    // [B, 1024, 512] attention out, TF-reshaped
__device__ float d_Wkvf[CIN * KVD];
__device__ float d_bkvf[KVD];
__device__ float d_Wqf [CIN * QD];
__device__ float d_bqf [QD];
__device__ float d_Wpf [COUT * COUT];
__device__ float d_bpf [COUT];

__device__ __forceinline__ float hswish(float x) {
    // x * clip(x+3, 0, 6) / 6  ==  x * saturate(x/6 + 0.5)
    return x * __saturatef(x * (1.0f / 6.0f) + 0.5f);
}

// ---------------------------------------------------------------------------
// Fold BN (per-output-channel affine) into weights + bias.
// Wf[k][n] = W[k][n] * s[n];  bf[n] = (b[n]-mean[n])*s[n] + beta[n]
// s[n] = gamma[n] * rsqrt(var[n]+eps)
// WHICH: 0 = kv, 1 = q, 2 = proj
// ---------------------------------------------------------------------------
template <int WHICH>
__global__ void fold_kernel(const float* __restrict__ W, const float* __restrict__ b,
                            const float* __restrict__ gam, const float* __restrict__ bet,
                            const float* __restrict__ mu, const float* __restrict__ var,
                            int K, int N) {
    float* Wf; float* bf;
    if (WHICH == 0)      { Wf = d_Wkvf; bf = d_bkvf; }
    else if (WHICH == 1) { Wf = d_Wqf;  bf = d_bqf;  }
    else                 { Wf = d_Wpf;  bf = d_bpf;  }
    int i = blockIdx.x * 256 + threadIdx.x;
    if (i < K * N) {
        int n = i % N;
        float s = gam[n] * rsqrtf(var[n] + EPSB);
        Wf[i] = W[i] * s;
    }
    if (i < N) {
        float s = gam[i] * rsqrtf(var[i] + EPSB);
        bf[i] = (b[i] - mu[i]) * s + bet[i];
    }
}

// ---------------------------------------------------------------------------
// Tiled SGEMM: C[M,N] = f(A[M,K]) @ W[K,N] + bias
// BM=128, BN=64, BK=16, 256 threads, 8x4 microtile.
// MODE 0: kv GEMM   (A = x,        C = d_kvbuf)
// MODE 1: q  GEMM   (A = x strided-gathered, C = d_qbuf)
// MODE 2: proj GEMM (A = hardswish(d_zbuf),  C = d_out)
// ---------------------------------------------------------------------------
template <int MODE>
__global__ __launch_bounds__(256) void gemm_kernel(const float* __restrict__ Ain,
                                                   float* __restrict__ Cout,
                                                   int M, int N, int K) {
    const float* W;  const float* bias;  float* C;  const float* A = Ain;
    if (MODE == 0)      { W = d_Wkvf; bias = d_bkvf; C = d_kvbuf; }
    else if (MODE == 1) { W = d_Wqf;  bias = d_bqf;  C = d_qbuf;  }
    else                { W = d_Wpf;  bias = d_bpf;  C = Cout; A = d_zbuf; }

    __shared__ float As[16][132];   // padded to kill store conflicts
    __shared__ float Bs[16][64];

    int tid  = threadIdx.x;
    int row0 = blockIdx.y * 128;
    int col0 = blockIdx.x * 64;
    int ty = tid >> 4, tx = tid & 15;

    float acc[8][4] = {};

    // A-load assignment: 2 float4 per thread (128 rows x 16 cols)
    int lrow[2], lc4[2];
    const float* aptr[2];
#pragma unroll
    for (int j = 0; j < 2; j++) {
        int idx = tid + j * 256;
        int r = idx >> 2, c4 = idx & 3;
        lrow[j] = r; lc4[j] = c4;
        int gr = row0 + r;
        int src;
        if (MODE == 1) {
            int bb = gr >> 10, ql = gr & 1023;
            int qy = ql >> 5, qx = ql & 31;
            src = (bb << 12) + (qy << 7) + (qx << 1);   // b*4096 + 2qy*64 + 2qx
        } else {
            src = gr;
        }
        aptr[j] = A + (size_t)src * K + c4 * 4;
    }
    int bkr = tid >> 4, bc4 = tid & 15;

    for (int k0 = 0; k0 < K; k0 += 16) {
#pragma unroll
        for (int j = 0; j < 2; j++) {
            float4 a = *(const float4*)(aptr[j] + k0);
            if (MODE == 2) { a.x = hswish(a.x); a.y = hswish(a.y); a.z = hswish(a.z); a.w = hswish(a.w); }
            As[lc4[j] * 4 + 0][lrow[j]] = a.x;
            As[lc4[j] * 4 + 1][lrow[j]] = a.y;
            As[lc4[j] * 4 + 2][lrow[j]] = a.z;
            As[lc4[j] * 4 + 3][lrow[j]] = a.w;
        }
        *(float4*)&Bs[bkr][bc4 * 4] =
            *(const float4*)(W + (size_t)(k0 + bkr) * N + col0 + bc4 * 4);
        __syncthreads();
#pragma unroll
        for (int k = 0; k < 16; k++) {
            float4 a0 = *(float4*)&As[k][ty * 8];
            float4 a1 = *(float4*)&As[k][ty * 8 + 4];
            float4 bv = *(float4*)&Bs[k][tx * 4];
            float ar[8] = {a0.x, a0.y, a0.z, a0.w, a1.x, a1.y, a1.z, a1.w};
            float br[4] = {bv.x, bv.y, bv.z, bv.w};
#pragma unroll
            for (int i = 0; i < 8; i++)
#pragma unroll
                for (int j = 0; j < 4; j++)
                    acc[i][j] += ar[i] * br[j];
        }
        __syncthreads();
    }

    float4 bv = *(const float4*)(bias + col0 + tx * 4);
#pragma unroll
    for (int i = 0; i < 8; i++) {
        int gr = row0 + ty * 8 + i;
        float4 o;
        o.x = acc[i][0] + bv.x; o.y = acc[i][1] + bv.y;
        o.z = acc[i][2] + bv.z; o.w = acc[i][3] + bv.w;
        *(float4*)(C + (size_t)gr * N + col0 + tx * 4) = o;
    }
}

// ---------------------------------------------------------------------------
// Flash attention: 1 thread = 1 query. grid (QLEN/128, H, B), 128 threads.
// K/V read from d_kvbuf [B,SEQ,H*80] (k: +0..15, v: +16..79 within head chunk).
// Output written pre-reshaped for the TF transpose:
//   Z[b][h*128 + 2d + (q>>9)][q&511] = av[b,h,q,d]
// ---------------------------------------------------------------------------
__global__ __launch_bounds__(128, 3) void attn_kernel() {
    __shared__ float Ks[32][16];
    __shared__ float Vs[32][64];

    int tid = threadIdx.x;
    int b = blockIdx.z, h = blockIdx.y;
    int q = blockIdx.x * 128 + tid;

    const float* kvbase = d_kvbuf + (size_t)b * SEQL * KVD + h * 80;
    const float* qp = d_qbuf + ((size_t)(b * QL + q)) * QD + h * KD;

    // q premultiplied by scale * log2(e): softmax done in base-2
    const float SC = 0.25f * 1.44269504088896340736f;
    float qr[16];
#pragma unroll
    for (int i = 0; i < 4; i++) {
        float4 v = *(const float4*)(qp + i * 4);
        qr[i * 4 + 0] = v.x * SC; qr[i * 4 + 1] = v.y * SC;
        qr[i * 4 + 2] = v.z * SC; qr[i * 4 + 3] = v.w * SC;
    }

    float m = -1e30f, l = 0.0f;
    float acc[64];
#pragma unroll
    for (int d = 0; d < 64; d++) acc[d] = 0.0f;

    for (int s0 = 0; s0 < SEQL; s0 += 32) {
        // cooperative loads: K tile 32x16 (1 float4/thread), V tile 32x64 (4/thread)
        {
            int r = tid >> 2, c = tid & 3;
            *(float4*)&Ks[r][c * 4] = *(const float4*)(kvbase + (size_t)(s0 + r) * KVD + c * 4);
        }
#pragma unroll
        for (int j = 0; j < 4; j++) {
            int idx = tid + j * 128;
            int r = idx >> 4, c = idx & 15;
            *(float4*)&Vs[r][c * 4] = *(const float4*)(kvbase + (size_t)(s0 + r) * KVD + 16 + c * 4);
        }
        __syncthreads();

        float sc[32];
        float tmax = -1e30f;
#pragma unroll
        for (int s = 0; s < 32; s++) {
            float4 k0 = *(float4*)&Ks[s][0];
            float4 k1 = *(float4*)&Ks[s][4];
            float4 k2 = *(float4*)&Ks[s][8];
            float4 k3 = *(float4*)&Ks[s][12];
            float d0 = qr[0] * k0.x + qr[1] * k0.y + qr[2] * k0.z + qr[3] * k0.w;
            float d1 = qr[4] * k1.x + qr[5] * k1.y + qr[6] * k1.z + qr[7] * k1.w;
            float d2 = qr[8] * k2.x + qr[9] * k2.y + qr[10] * k2.z + qr[11] * k2.w;
            float d3 = qr[12] * k3.x + qr[13] * k3.y + qr[14] * k3.z + qr[15] * k3.w;
            float s4 = (d0 + d1) + (d2 + d3);
            sc[s] = s4;
            tmax = fmaxf(tmax, s4);
        }

        float mn = fmaxf(m, tmax);
        float alpha = exp2f(m - mn);
        l *= alpha;
#pragma unroll
        for (int d = 0; d < 64; d++) acc[d] *= alpha;

#pragma unroll
        for (int s = 0; s < 32; s++) {
            float p = exp2f(sc[s] - mn);
            l += p;
#pragma unroll
            for (int d4 = 0; d4 < 16; d4++) {
                float4 v = *(float4*)&Vs[s][d4 * 4];
                acc[d4 * 4 + 0] += p * v.x;
                acc[d4 * 4 + 1] += p * v.y;
                acc[d4 * 4 + 2] += p * v.z;
                acc[d4 * 4 + 3] += p * v.w;
            }
        }
        m = mn;
        __syncthreads();
    }

    float rl = 1.0f / l;
    int qhi = q >> 9, qlo = q & 511;
    float* zb = d_zbuf + (size_t)b * QL * COUT;
#pragma unroll
    for (int d = 0; d < 64; d++) {
        zb[(size_t)(h * 128 + 2 * d + qhi) * COUT + qlo] = acc[d] * rl;
    }
}

// ---------------------------------------------------------------------------
// Launch
// inputs: x, Wkv, bkv, g_kv, b_kv, m_kv, v_kv, Wq, bq, g_q, b_q, m_q, v_q,
//         Wp, bp, g_p, b_p, m_p, v_p
// ---------------------------------------------------------------------------
extern "C" void kernel_launch(void* const* d_in, const int* in_sizes, int n_in,
                              void* d_out, int out_size) {
    const float* x    = (const float*)d_in[0];
    const float* Wkv  = (const float*)d_in[1];
    const float* bkv  = (const float*)d_in[2];
    const float* gkv  = (const float*)d_in[3];
    const float* bekv = (const float*)d_in[4];
    const float* mkv  = (const float*)d_in[5];
    const float* vkv  = (const float*)d_in[6];
    const float* Wq   = (const float*)d_in[7];
    const float* bq   = (const float*)d_in[8];
    const float* gq   = (const float*)d_in[9];
    const float* beq  = (const float*)d_in[10];
    const float* mq   = (const float*)d_in[11];
    const float* vq   = (const float*)d_in[12];
    const float* Wp   = (const float*)d_in[13];
    const float* bp   = (const float*)d_in[14];
    const float* gp   = (const float*)d_in[15];
    const float* bep  = (const float*)d_in[16];
    const float* mp   = (const float*)d_in[17];
    const float* vp   = (const float*)d_in[18];
    float* out = (float*)d_out;

    fold_kernel<0><<<(CIN * KVD + 255) / 256, 256>>>(Wkv, bkv, gkv, bekv, mkv, vkv, CIN, KVD);
    fold_kernel<1><<<(CIN * QD + 255) / 256, 256>>>(Wq, bq, gq, beq, mq, vq, CIN, QD);
    fold_kernel<2><<<(COUT * COUT + 255) / 256, 256>>>(Wp, bp, gp, bep, mp, vp, COUT, COUT);

    // kv = BN(x @ Wkv + b):  [32768, 256] x [256, 640]
    gemm_kernel<0><<<dim3(KVD / 64, (BB * SEQL) / 128), 256>>>(x, nullptr, BB * SEQL, KVD, CIN);
    // q  = BN(xq @ Wq + b):  [8192, 256] x [256, 128] with strided row gather
    gemm_kernel<1><<<dim3(QD / 64, (BB * QL) / 128), 256>>>(x, nullptr, BB * QL, QD, CIN);
    // fused flash attention -> d_zbuf (TF-reshaped)
    attn_kernel<<<dim3(QL / 128, HH, BB), 128>>>();
    // out = BN(hardswish(Z) @ Wp + b): [8192, 512] x [512, 512]
    gemm_kernel<2><<<dim3(COUT / 64, (BB * QL) / 128), 256>>>(nullptr, out, BB * QL, COUT, COUT);
}

// round 3
// speedup vs baseline: 1.3187x; 1.3187x over previous
#include <cuda_runtime.h>
#include <math.h>

// Problem constants
#define BB   8
#define SEQL 4096
#define QL   1024
#define CIN  256
#define KVD  640
#define QD   128
#define HH   8
#define KD   16
#define VD   64
#define COUT 512
#define EPSB 1e-3f

typedef unsigned long long ull;

// Intermediates as __device__ globals (no dynamic allocation allowed)
__device__ float d_kvbuf[BB * SEQL * KVD];   // [B, SEQ, 640]  (BN folded)
__device__ float d_qbuf [BB * QL * QD];      // [B, QLEN, 128] (BN folded)
__device__ float d_zbuf [BB * QL * COUT];    // [B, 1024, 512] attention out, TF-reshaped
__device__ float d_Wkvf[CIN * KVD];
__device__ float d_bkvf[KVD];
__device__ float d_Wqf [CIN * QD];
__device__ float d_bqf [QD];
__device__ float d_Wpf [COUT * COUT];
__device__ float d_bpf [COUT];

// ---- packed f32x2 helpers (sm_103a FFMA2 — only reachable via PTX) ----
__device__ __forceinline__ ull ffma2(ull a, ull b, ull c) {
    ull d;
    asm("fma.rn.f32x2 %0, %1, %2, %3;" : "=l"(d) : "l"(a), "l"(b), "l"(c));
    return d;
}
__device__ __forceinline__ ull dup2(float x) {
    ull d;
    asm("mov.b64 %0, {%1, %1};" : "=l"(d) : "f"(x));
    return d;
}
__device__ __forceinline__ float2 unpack2(ull v) {
    float2 r;
    asm("mov.b64 {%0, %1}, %2;" : "=f"(r.x), "=f"(r.y) : "l"(v));
    return r;
}
__device__ __forceinline__ float ex2(float x) {
    float y;
    asm("ex2.approx.ftz.f32 %0, %1;" : "=f"(y) : "f"(x));
    return y;
}

__device__ __forceinline__ float hswish(float x) {
    return x * __saturatef(x * (1.0f / 6.0f) + 0.5f);
}

// ---------------------------------------------------------------------------
// Fold BN into weights + bias.
// ---------------------------------------------------------------------------
template <int WHICH>
__global__ void fold_kernel(const float* __restrict__ W, const float* __restrict__ b,
                            const float* __restrict__ gam, const float* __restrict__ bet,
                            const float* __restrict__ mu, const float* __restrict__ var,
                            int K, int N) {
    float* Wf; float* bf;
    if (WHICH == 0)      { Wf = d_Wkvf; bf = d_bkvf; }
    else if (WHICH == 1) { Wf = d_Wqf;  bf = d_bqf;  }
    else                 { Wf = d_Wpf;  bf = d_bpf;  }
    int i = blockIdx.x * 256 + threadIdx.x;
    if (i < K * N) {
        int n = i % N;
        float s = gam[n] * rsqrtf(var[n] + EPSB);
        Wf[i] = W[i] * s;
    }
    if (i < N) {
        float s = gam[i] * rsqrtf(var[i] + EPSB);
        bf[i] = (b[i] - mu[i]) * s + bet[i];
    }
}

// ---------------------------------------------------------------------------
// Tiled SGEMM with packed FFMA2: C[M,N] = f(A[M,K]) @ W[K,N] + bias
// BM=128, BN=64, BK=16, 256 threads, 8x4 microtile (M packed in pairs).
// ---------------------------------------------------------------------------
template <int MODE>
__global__ __launch_bounds__(256) void gemm_kernel(const float* __restrict__ Ain,
                                                   float* __restrict__ Cout,
                                                   int M, int N, int K) {
    const float* W;  const float* bias;  float* C;  const float* A = Ain;
    if (MODE == 0)      { W = d_Wkvf; bias = d_bkvf; C = d_kvbuf; }
    else if (MODE == 1) { W = d_Wqf;  bias = d_bqf;  C = d_qbuf;  }
    else                { W = d_Wpf;  bias = d_bpf;  C = Cout; A = d_zbuf; }

    __shared__ float As[16][132];   // padded; rows contiguous in the second index
    __shared__ float Bs[16][64];

    int tid  = threadIdx.x;
    int row0 = blockIdx.y * 128;
    int col0 = blockIdx.x * 64;
    int ty = tid >> 4, tx = tid & 15;

    // acc2[i][j] holds C rows (ty*8+2i, ty*8+2i+1) at column col0+tx*4+j
    ull acc2[4][4] = {};

    int lrow[2], lc4[2];
    const float* aptr[2];
#pragma unroll
    for (int j = 0; j < 2; j++) {
        int idx = tid + j * 256;
        int r = idx >> 2, c4 = idx & 3;
        lrow[j] = r; lc4[j] = c4;
        int gr = row0 + r;
        int src;
        if (MODE == 1) {
            int bb = gr >> 10, ql = gr & 1023;
            int qy = ql >> 5, qx = ql & 31;
            src = (bb << 12) + (qy << 7) + (qx << 1);
        } else {
            src = gr;
        }
        aptr[j] = A + (size_t)src * K + c4 * 4;
    }
    int bkr = tid >> 4, bc4 = tid & 15;

    for (int k0 = 0; k0 < K; k0 += 16) {
#pragma unroll
        for (int j = 0; j < 2; j++) {
            float4 a = *(const float4*)(aptr[j] + k0);
            if (MODE == 2) { a.x = hswish(a.x); a.y = hswish(a.y); a.z = hswish(a.z); a.w = hswish(a.w); }
            As[lc4[j] * 4 + 0][lrow[j]] = a.x;
            As[lc4[j] * 4 + 1][lrow[j]] = a.y;
            As[lc4[j] * 4 + 2][lrow[j]] = a.z;
            As[lc4[j] * 4 + 3][lrow[j]] = a.w;
        }
        *(float4*)&Bs[bkr][bc4 * 4] =
            *(const float4*)(W + (size_t)(k0 + bkr) * N + col0 + bc4 * 4);
        __syncthreads();
#pragma unroll
        for (int k = 0; k < 16; k++) {
            // two LDS.128 = 4 packed row-pairs of A
            ull a2[4];
            {
                ulonglong2 p0 = *(ulonglong2*)&As[k][ty * 8];
                ulonglong2 p1 = *(ulonglong2*)&As[k][ty * 8 + 4];
                a2[0] = p0.x; a2[1] = p0.y; a2[2] = p1.x; a2[3] = p1.y;
            }
            float4 bv = *(float4*)&Bs[k][tx * 4];
            ull b2[4] = {dup2(bv.x), dup2(bv.y), dup2(bv.z), dup2(bv.w)};
#pragma unroll
            for (int i = 0; i < 4; i++)
#pragma unroll
                for (int j = 0; j < 4; j++)
                    acc2[i][j] = ffma2(a2[i], b2[j], acc2[i][j]);
        }
        __syncthreads();
    }

    float4 bv = *(const float4*)(bias + col0 + tx * 4);
#pragma unroll
    for (int i = 0; i < 4; i++) {
        float2 c0 = unpack2(acc2[i][0]);
        float2 c1 = unpack2(acc2[i][1]);
        float2 c2 = unpack2(acc2[i][2]);
        float2 c3 = unpack2(acc2[i][3]);
        int gr = row0 + ty * 8 + 2 * i;
        float4 o0 = {c0.x + bv.x, c1.x + bv.y, c2.x + bv.z, c3.x + bv.w};
        float4 o1 = {c0.y + bv.x, c1.y + bv.y, c2.y + bv.z, c3.y + bv.w};
        *(float4*)(C + (size_t)gr * N + col0 + tx * 4) = o0;
        *(float4*)(C + (size_t)(gr + 1) * N + col0 + tx * 4) = o1;
    }
}

// ---------------------------------------------------------------------------
// Flash attention, packed f32x2, no online max (scores are O(1) after BN; softmax
// is shift-invariant and exp2 of |s|<~50 is safe in fp32).
// 1 thread = 1 query. grid (QLEN/128, H, B), 128 threads.
// Output pre-reshaped: Z[b][h*128 + 2d + (q>>9)][q&511] = av[b,h,q,d]
// ---------------------------------------------------------------------------
__global__ __launch_bounds__(128, 4) void attn_kernel() {
    __shared__ float Ks[32][16];
    __shared__ float Vs[32][64];

    int tid = threadIdx.x;
    int b = blockIdx.z, h = blockIdx.y;
    int q = blockIdx.x * 128 + tid;

    const float* kvbase = d_kvbuf + (size_t)b * SEQL * KVD + h * 80;
    const float* qp = d_qbuf + ((size_t)(b * QL + q)) * QD + h * KD;

    // q premultiplied by scale * log2(e): softmax in base 2
    const float SC = 0.25f * 1.44269504088896340736f;
    ull q2[8];
#pragma unroll
    for (int i = 0; i < 4; i++) {
        float4 v = *(const float4*)(qp + i * 4);
        float2 p0 = {v.x * SC, v.y * SC};
        float2 p1 = {v.z * SC, v.w * SC};
        q2[i * 2 + 0] = *(ull*)&p0;
        q2[i * 2 + 1] = *(ull*)&p1;
    }

    float l = 0.0f;
    ull acc2[32];   // packed pairs over the 64 V dims
#pragma unroll
    for (int j = 0; j < 32; j++) acc2[j] = 0ULL;

    for (int s0 = 0; s0 < SEQL; s0 += 32) {
        // cooperative loads: K tile 32x16 (1 float4/thread), V tile 32x64 (4/thread)
        {
            int r = tid >> 2, c = tid & 3;
            *(float4*)&Ks[r][c * 4] = *(const float4*)(kvbase + (size_t)(s0 + r) * KVD + c * 4);
        }
#pragma unroll
        for (int j = 0; j < 4; j++) {
            int idx = tid + j * 128;
            int r = idx >> 4, c = idx & 15;
            *(float4*)&Vs[r][c * 4] = *(const float4*)(kvbase + (size_t)(s0 + r) * KVD + 16 + c * 4);
        }
        __syncthreads();

#pragma unroll 4
        for (int s = 0; s < 32; s++) {
            // QK dot via 8 packed FMAs + horizontal add
            const ulonglong2* kp = (const ulonglong2*)&Ks[s][0];
            ull d2 = 0ULL;
            ulonglong2 k01 = kp[0], k23 = kp[1], k45 = kp[2], k67 = kp[3];
            d2 = ffma2(q2[0], k01.x, d2);
            d2 = ffma2(q2[1], k01.y, d2);
            d2 = ffma2(q2[2], k23.x, d2);
            d2 = ffma2(q2[3], k23.y, d2);
            d2 = ffma2(q2[4], k45.x, d2);
            d2 = ffma2(q2[5], k45.y, d2);
            d2 = ffma2(q2[6], k67.x, d2);
            d2 = ffma2(q2[7], k67.y, d2);
            float2 dh = unpack2(d2);
            float p = ex2(dh.x + dh.y);
            l += p;
            ull p2 = dup2(p);

            const ulonglong2* vp = (const ulonglong2*)&Vs[s][0];
#pragma unroll
            for (int j = 0; j < 16; j++) {
                ulonglong2 vv = vp[j];
                acc2[2 * j + 0] = ffma2(p2, vv.x, acc2[2 * j + 0]);
                acc2[2 * j + 1] = ffma2(p2, vv.y, acc2[2 * j + 1]);
            }
        }
        __syncthreads();
    }

    float rl = 1.0f / l;
    int qhi = q >> 9, qlo = q & 511;
    float* zb = d_zbuf + (size_t)b * QL * COUT + (size_t)(h * 128 + qhi) * COUT + qlo;
#pragma unroll
    for (int j = 0; j < 32; j++) {
        float2 a = unpack2(acc2[j]);
        zb[(size_t)(4 * j) * COUT]     = a.x * rl;   // d = 2j   -> row offset 2*(2j)
        zb[(size_t)(4 * j + 2) * COUT] = a.y * rl;   // d = 2j+1 -> row offset 2*(2j+1)
    }
}

// ---------------------------------------------------------------------------
// Launch
// ---------------------------------------------------------------------------
extern "C" void kernel_launch(void* const* d_in, const int* in_sizes, int n_in,
                              void* d_out, int out_size) {
    const float* x    = (const float*)d_in[0];
    const float* Wkv  = (const float*)d_in[1];
    const float* bkv  = (const float*)d_in[2];
    const float* gkv  = (const float*)d_in[3];
    const float* bekv = (const float*)d_in[4];
    const float* mkv  = (const float*)d_in[5];
    const float* vkv  = (const float*)d_in[6];
    const float* Wq   = (const float*)d_in[7];
    const float* bq   = (const float*)d_in[8];
    const float* gq   = (const float*)d_in[9];
    const float* beq  = (const float*)d_in[10];
    const float* mq   = (const float*)d_in[11];
    const float* vq   = (const float*)d_in[12];
    const float* Wp   = (const float*)d_in[13];
    const float* bp   = (const float*)d_in[14];
    const float* gp   = (const float*)d_in[15];
    const float* bep  = (const float*)d_in[16];
    const float* mp   = (const float*)d_in[17];
    const float* vp   = (const float*)d_in[18];
    float* out = (float*)d_out;

    fold_kernel<0><<<(CIN * KVD + 255) / 256, 256>>>(Wkv, bkv, gkv, bekv, mkv, vkv, CIN, KVD);
    fold_kernel<1><<<(CIN * QD + 255) / 256, 256>>>(Wq, bq, gq, beq, mq, vq, CIN, QD);
    fold_kernel<2><<<(COUT * COUT + 255) / 256, 256>>>(Wp, bp, gp, bep, mp, vp, COUT, COUT);

    gemm_kernel<0><<<dim3(KVD / 64, (BB * SEQL) / 128), 256>>>(x, nullptr, BB * SEQL, KVD, CIN);
    gemm_kernel<1><<<dim3(QD / 64, (BB * QL) / 128), 256>>>(x, nullptr, BB * QL, QD, CIN);
    attn_kernel<<<dim3(QL / 128, HH, BB), 128>>>();
    gemm_kernel<2><<<dim3(COUT / 64, (BB * QL) / 128), 256>>>(nullptr, out, BB * QL, COUT, COUT);
}

// round 4
// speedup vs baseline: 1.5437x; 1.1706x over previous
#include <cuda_runtime.h>
#include <math.h>

// Problem constants
#define BB   8
#define SEQL 4096
#define QL   1024
#define CIN  256
#define KVD  640
#define QD   128
#define HH   8
#define KD   16
#define VD   64
#define COUT 512
#define EPSB 1e-3f

typedef unsigned long long ull;

// Intermediates as __device__ globals (no dynamic allocation allowed)
__device__ float d_kvbuf[BB * SEQL * KVD];   // [B, SEQ, 640]  (BN folded)
__device__ float d_qbuf [BB * QL * QD];      // [B, QLEN, 128] (BN folded)
__device__ float d_zbuf [BB * QL * COUT];    // [B, 1024, 512] attention out, TF-reshaped
__device__ float d_Wkvf[CIN * KVD];
__device__ float d_bkvf[KVD];
__device__ float d_Wqf [CIN * QD];
__device__ float d_bqf [QD];
__device__ float d_Wpf [COUT * COUT];
__device__ float d_bpf [COUT];

// ---- packed f32x2 helpers (sm_103a FFMA2 — only reachable via PTX) ----
__device__ __forceinline__ ull ffma2(ull a, ull b, ull c) {
    ull d;
    asm("fma.rn.f32x2 %0, %1, %2, %3;" : "=l"(d) : "l"(a), "l"(b), "l"(c));
    return d;
}
__device__ __forceinline__ ull dup2(float x) {
    ull d;
    asm("mov.b64 %0, {%1, %1};" : "=l"(d) : "f"(x));
    return d;
}
__device__ __forceinline__ float2 unpack2(ull v) {
    float2 r;
    asm("mov.b64 {%0, %1}, %2;" : "=f"(r.x), "=f"(r.y) : "l"(v));
    return r;
}
__device__ __forceinline__ float ex2(float x) {
    float y;
    asm("ex2.approx.ftz.f32 %0, %1;" : "=f"(y) : "f"(x));
    return y;
}

__device__ __forceinline__ float hswish(float x) {
    return x * __saturatef(x * (1.0f / 6.0f) + 0.5f);
}

// ---------------------------------------------------------------------------
// Fold BN into weights + bias.
// ---------------------------------------------------------------------------
template <int WHICH>
__global__ void fold_kernel(const float* __restrict__ W, const float* __restrict__ b,
                            const float* __restrict__ gam, const float* __restrict__ bet,
                            const float* __restrict__ mu, const float* __restrict__ var,
                            int K, int N) {
    float* Wf; float* bf;
    if (WHICH == 0)      { Wf = d_Wkvf; bf = d_bkvf; }
    else if (WHICH == 1) { Wf = d_Wqf;  bf = d_bqf;  }
    else                 { Wf = d_Wpf;  bf = d_bpf;  }
    int i = blockIdx.x * 256 + threadIdx.x;
    if (i < K * N) {
        int n = i % N;
        float s = gam[n] * rsqrtf(var[n] + EPSB);
        Wf[i] = W[i] * s;
    }
    if (i < N) {
        float s = gam[i] * rsqrtf(var[i] + EPSB);
        bf[i] = (b[i] - mu[i]) * s + bet[i];
    }
}

// ---------------------------------------------------------------------------
// Tiled SGEMM, packed FFMA2: C[M,N] = f(A[M,K]) @ W[K,N] + bias
// BM=128, BN=128, BK=16, 256 threads, 8x8 microtile (rows packed in pairs).
// ---------------------------------------------------------------------------
template <int MODE>
__global__ __launch_bounds__(256) void gemm_kernel(const float* __restrict__ Ain,
                                                   float* __restrict__ Cout,
                                                   int M, int N, int K) {
    const float* W;  const float* bias;  float* C;  const float* A = Ain;
    if (MODE == 0)      { W = d_Wkvf; bias = d_bkvf; C = d_kvbuf; }
    else if (MODE == 1) { W = d_Wqf;  bias = d_bqf;  C = d_qbuf;  }
    else                { W = d_Wpf;  bias = d_bpf;  C = Cout; A = d_zbuf; }

    __shared__ float As[16][132];   // A^T tile, padded
    __shared__ float Bs[16][128];

    int tid  = threadIdx.x;
    int row0 = blockIdx.y * 128;
    int col0 = blockIdx.x * 128;
    int ty = tid >> 4, tx = tid & 15;

    // acc2[i][j]: C rows (ty*8+2i, ty*8+2i+1), col col0 + tx*8 + j
    ull acc2[4][8] = {};

    // A-load assignment: 2 float4 per thread (128 rows x 16 cols)
    int lrow[2], lc4[2];
    const float* aptr[2];
#pragma unroll
    for (int j = 0; j < 2; j++) {
        int idx = tid + j * 256;
        int r = idx >> 2, c4 = idx & 3;
        lrow[j] = r; lc4[j] = c4;
        int gr = row0 + r;
        int src;
        if (MODE == 1) {
            int bb = gr >> 10, ql = gr & 1023;
            int qy = ql >> 5, qx = ql & 31;
            src = (bb << 12) + (qy << 7) + (qx << 1);
        } else {
            src = gr;
        }
        aptr[j] = A + (size_t)src * K + c4 * 4;
    }
    // B-load: 2 float4 per thread (16 rows x 128 cols)
    int br_[2], bc_[2];
#pragma unroll
    for (int j = 0; j < 2; j++) {
        int idx = tid + j * 256;
        br_[j] = idx >> 5; bc_[j] = (idx & 31) * 4;
    }

    for (int k0 = 0; k0 < K; k0 += 16) {
#pragma unroll
        for (int j = 0; j < 2; j++) {
            float4 a = *(const float4*)(aptr[j] + k0);
            if (MODE == 2) { a.x = hswish(a.x); a.y = hswish(a.y); a.z = hswish(a.z); a.w = hswish(a.w); }
            As[lc4[j] * 4 + 0][lrow[j]] = a.x;
            As[lc4[j] * 4 + 1][lrow[j]] = a.y;
            As[lc4[j] * 4 + 2][lrow[j]] = a.z;
            As[lc4[j] * 4 + 3][lrow[j]] = a.w;
        }
#pragma unroll
        for (int j = 0; j < 2; j++) {
            *(float4*)&Bs[br_[j]][bc_[j]] =
                *(const float4*)(W + (size_t)(k0 + br_[j]) * N + col0 + bc_[j]);
        }
        __syncthreads();
#pragma unroll
        for (int k = 0; k < 16; k++) {
            ull a2[4];
            {
                ulonglong2 p0 = *(ulonglong2*)&As[k][ty * 8];
                ulonglong2 p1 = *(ulonglong2*)&As[k][ty * 8 + 4];
                a2[0] = p0.x; a2[1] = p0.y; a2[2] = p1.x; a2[3] = p1.y;
            }
            float4 b0 = *(float4*)&Bs[k][tx * 8];
            float4 b1 = *(float4*)&Bs[k][tx * 8 + 4];
            ull b2[8] = {dup2(b0.x), dup2(b0.y), dup2(b0.z), dup2(b0.w),
                         dup2(b1.x), dup2(b1.y), dup2(b1.z), dup2(b1.w)};
#pragma unroll
            for (int i = 0; i < 4; i++)
#pragma unroll
                for (int j = 0; j < 8; j++)
                    acc2[i][j] = ffma2(a2[i], b2[j], acc2[i][j]);
        }
        __syncthreads();
    }

    float4 bv0 = *(const float4*)(bias + col0 + tx * 8);
    float4 bv1 = *(const float4*)(bias + col0 + tx * 8 + 4);
    float bb8[8] = {bv0.x, bv0.y, bv0.z, bv0.w, bv1.x, bv1.y, bv1.z, bv1.w};
#pragma unroll
    for (int i = 0; i < 4; i++) {
        float r0[8], r1[8];
#pragma unroll
        for (int j = 0; j < 8; j++) {
            float2 c = unpack2(acc2[i][j]);
            r0[j] = c.x + bb8[j];
            r1[j] = c.y + bb8[j];
        }
        int gr = row0 + ty * 8 + 2 * i;
        float* p0 = C + (size_t)gr * N + col0 + tx * 8;
        float* p1 = p0 + N;
        *(float4*)p0       = *(float4*)&r0[0];
        *(float4*)(p0 + 4) = *(float4*)&r0[4];
        *(float4*)p1       = *(float4*)&r1[0];
        *(float4*)(p1 + 4) = *(float4*)&r1[4];
    }
}

// ---------------------------------------------------------------------------
// Flash attention, 2 queries per thread (q0 and q0+512), packed f32x2, no
// online max (scores O(1) after BN; softmax shift-invariant, exp2 safe).
// grid (512/128, H, B), 128 threads. K/V smem tiles shared by both queries.
// Output pre-reshaped: Z[b][h*128 + 2d + (q>>9)][q&511] = av[b,h,q,d]
//   pairing q1 = q0 + 512 -> adjacent rows 2d / 2d+1, same column q0.
// ---------------------------------------------------------------------------
__global__ __launch_bounds__(128, 2) void attn_kernel() {
    __shared__ float Ks[32][16];
    __shared__ float Vs[32][64];

    int tid = threadIdx.x;
    int b = blockIdx.z, h = blockIdx.y;
    int q0 = blockIdx.x * 128 + tid;          // 0..511

    const float* kvbase = d_kvbuf + (size_t)b * SEQL * KVD + h * 80;
    const float* qpa = d_qbuf + ((size_t)(b * QL + q0)) * QD + h * KD;
    const float* qpb = qpa + (size_t)512 * QD;

    const float SC = 0.25f * 1.44269504088896340736f;
    ull q2a[8], q2b[8];
#pragma unroll
    for (int i = 0; i < 4; i++) {
        float4 v = *(const float4*)(qpa + i * 4);
        float2 p0 = {v.x * SC, v.y * SC};
        float2 p1 = {v.z * SC, v.w * SC};
        q2a[i * 2 + 0] = *(ull*)&p0;
        q2a[i * 2 + 1] = *(ull*)&p1;
        float4 w = *(const float4*)(qpb + i * 4);
        float2 p2 = {w.x * SC, w.y * SC};
        float2 p3 = {w.z * SC, w.w * SC};
        q2b[i * 2 + 0] = *(ull*)&p2;
        q2b[i * 2 + 1] = *(ull*)&p3;
    }

    float la = 0.0f, lb = 0.0f;
    ull acca[32], accb[32];
#pragma unroll
    for (int j = 0; j < 32; j++) { acca[j] = 0ULL; accb[j] = 0ULL; }

    for (int s0 = 0; s0 < SEQL; s0 += 32) {
        {
            int r = tid >> 2, c = tid & 3;
            *(float4*)&Ks[r][c * 4] = *(const float4*)(kvbase + (size_t)(s0 + r) * KVD + c * 4);
        }
#pragma unroll
        for (int j = 0; j < 4; j++) {
            int idx = tid + j * 128;
            int r = idx >> 4, c = idx & 15;
            *(float4*)&Vs[r][c * 4] = *(const float4*)(kvbase + (size_t)(s0 + r) * KVD + 16 + c * 4);
        }
        __syncthreads();

#pragma unroll 2
        for (int s = 0; s < 32; s++) {
            const ulonglong2* kp = (const ulonglong2*)&Ks[s][0];
            ulonglong2 k01 = kp[0], k23 = kp[1], k45 = kp[2], k67 = kp[3];
            ull da = 0ULL, db = 0ULL;
            da = ffma2(q2a[0], k01.x, da);  db = ffma2(q2b[0], k01.x, db);
            da = ffma2(q2a[1], k01.y, da);  db = ffma2(q2b[1], k01.y, db);
            da = ffma2(q2a[2], k23.x, da);  db = ffma2(q2b[2], k23.x, db);
            da = ffma2(q2a[3], k23.y, da);  db = ffma2(q2b[3], k23.y, db);
            da = ffma2(q2a[4], k45.x, da);  db = ffma2(q2b[4], k45.x, db);
            da = ffma2(q2a[5], k45.y, da);  db = ffma2(q2b[5], k45.y, db);
            da = ffma2(q2a[6], k67.x, da);  db = ffma2(q2b[6], k67.x, db);
            da = ffma2(q2a[7], k67.y, da);  db = ffma2(q2b[7], k67.y, db);
            float2 ha = unpack2(da), hb = unpack2(db);
            float pa = ex2(ha.x + ha.y);
            float pb = ex2(hb.x + hb.y);
            la += pa;  lb += pb;
            ull p2a = dup2(pa), p2b = dup2(pb);

            const ulonglong2* vp = (const ulonglong2*)&Vs[s][0];
#pragma unroll
            for (int j = 0; j < 16; j++) {
                ulonglong2 vv = vp[j];
                acca[2 * j + 0] = ffma2(p2a, vv.x, acca[2 * j + 0]);
                acca[2 * j + 1] = ffma2(p2a, vv.y, acca[2 * j + 1]);
                accb[2 * j + 0] = ffma2(p2b, vv.x, accb[2 * j + 0]);
                accb[2 * j + 1] = ffma2(p2b, vv.y, accb[2 * j + 1]);
            }
        }
        __syncthreads();
    }

    float ra = 1.0f / la, rb = 1.0f / lb;
    // q0 -> qhi=0, q1=q0+512 -> qhi=1, both at column q0.
    float* zb = d_zbuf + (size_t)b * QL * COUT + (size_t)(h * 128) * COUT + q0;
#pragma unroll
    for (int j = 0; j < 32; j++) {
        float2 a = unpack2(acca[j]);
        float2 bv = unpack2(accb[j]);
        zb[(size_t)(4 * j + 0) * COUT] = a.x * ra;   // d=2j,   q0
        zb[(size_t)(4 * j + 1) * COUT] = bv.x * rb;  // d=2j,   q1
        zb[(size_t)(4 * j + 2) * COUT] = a.y * ra;   // d=2j+1, q0
        zb[(size_t)(4 * j + 3) * COUT] = bv.y * rb;  // d=2j+1, q1
    }
}

// ---------------------------------------------------------------------------
// Launch
// ---------------------------------------------------------------------------
extern "C" void kernel_launch(void* const* d_in, const int* in_sizes, int n_in,
                              void* d_out, int out_size) {
    const float* x    = (const float*)d_in[0];
    const float* Wkv  = (const float*)d_in[1];
    const float* bkv  = (const float*)d_in[2];
    const float* gkv  = (const float*)d_in[3];
    const float* bekv = (const float*)d_in[4];
    const float* mkv  = (const float*)d_in[5];
    const float* vkv  = (const float*)d_in[6];
    const float* Wq   = (const float*)d_in[7];
    const float* bq   = (const float*)d_in[8];
    const float* gq   = (const float*)d_in[9];
    const float* beq  = (const float*)d_in[10];
    const float* mq   = (const float*)d_in[11];
    const float* vq   = (const float*)d_in[12];
    const float* Wp   = (const float*)d_in[13];
    const float* bp   = (const float*)d_in[14];
    const float* gp   = (const float*)d_in[15];
    const float* bep  = (const float*)d_in[16];
    const float* mp   = (const float*)d_in[17];
    const float* vp   = (const float*)d_in[18];
    float* out = (float*)d_out;

    fold_kernel<0><<<(CIN * KVD + 255) / 256, 256>>>(Wkv, bkv, gkv, bekv, mkv, vkv, CIN, KVD);
    fold_kernel<1><<<(CIN * QD + 255) / 256, 256>>>(Wq, bq, gq, beq, mq, vq, CIN, QD);
    fold_kernel<2><<<(COUT * COUT + 255) / 256, 256>>>(Wp, bp, gp, bep, mp, vp, COUT, COUT);

    // kv = BN(x @ Wkv + b):  [32768,256]x[256,640]
    gemm_kernel<0><<<dim3(KVD / 128, (BB * SEQL) / 128), 256>>>(x, nullptr, BB * SEQL, KVD, CIN);
    // q  = BN(xq @ Wq + b):  [8192,256]x[256,128] (strided row gather)
    gemm_kernel<1><<<dim3(QD / 128, (BB * QL) / 128), 256>>>(x, nullptr, BB * QL, QD, CIN);
    // fused flash attention -> d_zbuf (TF-reshaped), 2 queries/thread
    attn_kernel<<<dim3(4, HH, BB), 128>>>();
    // out = BN(hardswish(Z) @ Wp + b): [8192,512]x[512,512]
    gemm_kernel<2><<<dim3(COUT / 128, (BB * QL) / 128), 256>>>(nullptr, out, BB * QL, COUT, COUT);
}

// round 5
// speedup vs baseline: 1.6325x; 1.0575x over previous
#include <cuda_runtime.h>
#include <math.h>
#include <stdint.h>

// Problem constants
#define BB   8
#define SEQL 4096
#define QL   1024
#define CIN  256
#define KVD  640
#define QD   128
#define HH   8
#define KD   16
#define VD   64
#define COUT 512
#define EPSB 1e-3f

typedef unsigned long long ull;

// Intermediates as __device__ globals (no dynamic allocation allowed)
__device__ float d_kvbuf[BB * SEQL * KVD];   // [B, SEQ, 640]  (BN folded)
__device__ float d_qbuf [BB * QL * QD];      // [B, QLEN, 128] (BN folded)
__device__ float d_zbuf [BB * QL * COUT];    // [B, 1024, 512] attention out, TF-reshaped
__device__ float d_Wkvf[CIN * KVD];
__device__ float d_bkvf[KVD];
__device__ float d_Wqf [CIN * QD];
__device__ float d_bqf [QD];
__device__ float d_Wpf [COUT * COUT];
__device__ float d_bpf [COUT];

// ---- packed f32x2 helpers (sm_103a FFMA2 — only reachable via PTX) ----
__device__ __forceinline__ ull ffma2(ull a, ull b, ull c) {
    ull d;
    asm("fma.rn.f32x2 %0, %1, %2, %3;" : "=l"(d) : "l"(a), "l"(b), "l"(c));
    return d;
}
__device__ __forceinline__ ull add2(ull a, ull b) {
    ull d;
    asm("add.rn.f32x2 %0, %1, %2;" : "=l"(d) : "l"(a), "l"(b));
    return d;
}
__device__ __forceinline__ ull dup2(float x) {
    ull d;
    asm("mov.b64 %0, {%1, %1};" : "=l"(d) : "f"(x));
    return d;
}
__device__ __forceinline__ float2 unpack2(ull v) {
    float2 r;
    asm("mov.b64 {%0, %1}, %2;" : "=f"(r.x), "=f"(r.y) : "l"(v));
    return r;
}
__device__ __forceinline__ float ex2(float x) {
    float y;
    asm("ex2.approx.ftz.f32 %0, %1;" : "=f"(y) : "f"(x));
    return y;
}
__device__ __forceinline__ uint32_t s2u(const void* p) {
    return (uint32_t)__cvta_generic_to_shared(p);
}
__device__ __forceinline__ void cpasync16(uint32_t dst, const void* src) {
    asm volatile("cp.async.cg.shared.global [%0], [%1], 16;" :: "r"(dst), "l"(src));
}
#define CP_COMMIT() asm volatile("cp.async.commit_group;")
#define CP_WAIT1()  asm volatile("cp.async.wait_group 1;")

__device__ __forceinline__ float hswish(float x) {
    return x * __saturatef(x * (1.0f / 6.0f) + 0.5f);
}

// ---------------------------------------------------------------------------
// Fold BN into weights + bias.
// ---------------------------------------------------------------------------
template <int WHICH>
__global__ void fold_kernel(const float* __restrict__ W, const float* __restrict__ b,
                            const float* __restrict__ gam, const float* __restrict__ bet,
                            const float* __restrict__ mu, const float* __restrict__ var,
                            int K, int N) {
    float* Wf; float* bf;
    if (WHICH == 0)      { Wf = d_Wkvf; bf = d_bkvf; }
    else if (WHICH == 1) { Wf = d_Wqf;  bf = d_bqf;  }
    else                 { Wf = d_Wpf;  bf = d_bpf;  }
    int i = blockIdx.x * 256 + threadIdx.x;
    if (i < K * N) {
        int n = i % N;
        float s = gam[n] * rsqrtf(var[n] + EPSB);
        Wf[i] = W[i] * s;
    }
    if (i < N) {
        float s = gam[i] * rsqrtf(var[i] + EPSB);
        bf[i] = (b[i] - mu[i]) * s + bet[i];
    }
}

// ---------------------------------------------------------------------------
// Tiled SGEMM, packed FFMA2: C[M,N] = f(A[M,K]) @ W[K,N] + bias
// BM=128, BN=128, BK=16, 256 threads.
// Microtile M16 (8 packed row-pairs) x N4: A pairs come packed from smem,
// only 4 dup2 per 32 FFMA2.
// ---------------------------------------------------------------------------
template <int MODE>
__global__ __launch_bounds__(256) void gemm_kernel(const float* __restrict__ Ain,
                                                   float* __restrict__ Cout,
                                                   int M, int N, int K) {
    const float* W;  const float* bias;  float* C;  const float* A = Ain;
    if (MODE == 0)      { W = d_Wkvf; bias = d_bkvf; C = d_kvbuf; }
    else if (MODE == 1) { W = d_Wqf;  bias = d_bqf;  C = d_qbuf;  }
    else                { W = d_Wpf;  bias = d_bpf;  C = Cout; A = d_zbuf; }

    __shared__ __align__(16) float As[16][132];   // A^T tile [k][row], padded
    __shared__ __align__(16) float Bs[16][128];

    int tid  = threadIdx.x;
    int row0 = blockIdx.y * 128;
    int col0 = blockIdx.x * 128;
    int ty = tid >> 5;          // 0..7  : 16-row group
    int tx = tid & 31;          // 0..31 : 4-col group

    // acc2[i][j]: C rows (ty*16+2i, ty*16+2i+1), col col0 + tx*4 + j
    ull acc2[8][4] = {};

    // A-load assignment: 2 float4 per thread (128 rows x 16 cols)
    int lrow[2], lc4[2];
    const float* aptr[2];
#pragma unroll
    for (int j = 0; j < 2; j++) {
        int idx = tid + j * 256;
        int r = idx >> 2, c4 = idx & 3;
        lrow[j] = r; lc4[j] = c4;
        int gr = row0 + r;
        int src;
        if (MODE == 1) {
            int bb = gr >> 10, ql = gr & 1023;
            int qy = ql >> 5, qx = ql & 31;
            src = (bb << 12) + (qy << 7) + (qx << 1);
        } else {
            src = gr;
        }
        aptr[j] = A + (size_t)src * K + c4 * 4;
    }
    // B-load: 2 float4 per thread (16 rows x 128 cols)
    int br_[2], bc_[2];
#pragma unroll
    for (int j = 0; j < 2; j++) {
        int idx = tid + j * 256;
        br_[j] = idx >> 5; bc_[j] = (idx & 31) * 4;
    }

    for (int k0 = 0; k0 < K; k0 += 16) {
#pragma unroll
        for (int j = 0; j < 2; j++) {
            float4 a = *(const float4*)(aptr[j] + k0);
            if (MODE == 2) { a.x = hswish(a.x); a.y = hswish(a.y); a.z = hswish(a.z); a.w = hswish(a.w); }
            As[lc4[j] * 4 + 0][lrow[j]] = a.x;
            As[lc4[j] * 4 + 1][lrow[j]] = a.y;
            As[lc4[j] * 4 + 2][lrow[j]] = a.z;
            As[lc4[j] * 4 + 3][lrow[j]] = a.w;
        }
#pragma unroll
        for (int j = 0; j < 2; j++) {
            *(float4*)&Bs[br_[j]][bc_[j]] =
                *(const float4*)(W + (size_t)(k0 + br_[j]) * N + col0 + bc_[j]);
        }
        __syncthreads();
#pragma unroll
        for (int k = 0; k < 16; k++) {
            // 16 A rows = 8 packed pairs, straight from smem (broadcast within warp)
            ull a2[8];
            {
                ulonglong2 p0 = *(ulonglong2*)&As[k][ty * 16];
                ulonglong2 p1 = *(ulonglong2*)&As[k][ty * 16 + 4];
                ulonglong2 p2 = *(ulonglong2*)&As[k][ty * 16 + 8];
                ulonglong2 p3 = *(ulonglong2*)&As[k][ty * 16 + 12];
                a2[0] = p0.x; a2[1] = p0.y; a2[2] = p1.x; a2[3] = p1.y;
                a2[4] = p2.x; a2[5] = p2.y; a2[6] = p3.x; a2[7] = p3.y;
            }
            float4 bv = *(float4*)&Bs[k][tx * 4];
            ull b2[4] = {dup2(bv.x), dup2(bv.y), dup2(bv.z), dup2(bv.w)};
#pragma unroll
            for (int i = 0; i < 8; i++)
#pragma unroll
                for (int j = 0; j < 4; j++)
                    acc2[i][j] = ffma2(a2[i], b2[j], acc2[i][j]);
        }
        __syncthreads();
    }

    float4 bv = *(const float4*)(bias + col0 + tx * 4);
    float bb4[4] = {bv.x, bv.y, bv.z, bv.w};
#pragma unroll
    for (int i = 0; i < 8; i++) {
        float r0[4], r1[4];
#pragma unroll
        for (int j = 0; j < 4; j++) {
            float2 c = unpack2(acc2[i][j]);
            r0[j] = c.x + bb4[j];
            r1[j] = c.y + bb4[j];
        }
        int gr = row0 + ty * 16 + 2 * i;
        float* p0 = C + (size_t)gr * N + col0 + tx * 4;
        *(float4*)p0       = *(float4*)&r0[0];
        *(float4*)(p0 + N) = *(float4*)&r1[0];
    }
}

// ---------------------------------------------------------------------------
// Flash attention, 2 queries per thread (q0 and q0+512), packed f32x2,
// cp.async double-buffered K/V tiles, split QK chains, no online max
// (scores O(1) after BN; softmax shift-invariant, exp2 safe in fp32).
// grid (4, H, B), 128 threads.
// Output pre-reshaped: Z[b][h*128 + 2d + (q>>9)][q&511] = av[b,h,q,d]
// ---------------------------------------------------------------------------
__global__ __launch_bounds__(128, 2) void attn_kernel() {
    __shared__ __align__(16) float Ks[2][32][16];
    __shared__ __align__(16) float Vs[2][32][64];

    int tid = threadIdx.x;
    int b = blockIdx.z, h = blockIdx.y;
    int q0 = blockIdx.x * 128 + tid;          // 0..511

    const float* kvbase = d_kvbuf + (size_t)b * SEQL * KVD + h * 80;
    const float* qpa = d_qbuf + ((size_t)(b * QL + q0)) * QD + h * KD;
    const float* qpb = qpa + (size_t)512 * QD;

    // --- tile-load assignments (cp.async, 16B each) ---
    int kr = tid >> 2, kc = (tid & 3) * 4;                 // K tile: 1 per thread
    const float* kg = kvbase + (size_t)kr * KVD + kc;
    uint32_t ksm[2] = { s2u(&Ks[0][kr][kc]), s2u(&Ks[1][kr][kc]) };
    const float* vg[4];
    uint32_t vsm[2][4];
#pragma unroll
    for (int j = 0; j < 4; j++) {
        int idx = tid + j * 128;
        int r = idx >> 4, c = (idx & 15) * 4;
        vg[j] = kvbase + (size_t)r * KVD + 16 + c;
        vsm[0][j] = s2u(&Vs[0][r][c]);
        vsm[1][j] = s2u(&Vs[1][r][c]);
    }

    const float SC = 0.25f * 1.44269504088896340736f;
    ull q2a[8], q2b[8];
#pragma unroll
    for (int i = 0; i < 4; i++) {
        float4 v = *(const float4*)(qpa + i * 4);
        float2 p0 = {v.x * SC, v.y * SC};
        float2 p1 = {v.z * SC, v.w * SC};
        q2a[i * 2 + 0] = *(ull*)&p0;
        q2a[i * 2 + 1] = *(ull*)&p1;
        float4 w = *(const float4*)(qpb + i * 4);
        float2 p2 = {w.x * SC, w.y * SC};
        float2 p3 = {w.z * SC, w.w * SC};
        q2b[i * 2 + 0] = *(ull*)&p2;
        q2b[i * 2 + 1] = *(ull*)&p3;
    }

    float la = 0.0f, lb = 0.0f;
    ull acca[32], accb[32];
#pragma unroll
    for (int j = 0; j < 32; j++) { acca[j] = 0ULL; accb[j] = 0ULL; }

    // prefetch tile 0
    {
        cpasync16(ksm[0], kg);
#pragma unroll
        for (int j = 0; j < 4; j++) cpasync16(vsm[0][j], vg[j]);
    }
    CP_COMMIT();

    const int NT = SEQL / 32;   // 128 tiles
    for (int t = 0; t < NT; ++t) {
        if (t + 1 < NT) {
            size_t off = (size_t)(t + 1) * 32 * KVD;
            int bf = (t + 1) & 1;
            cpasync16(ksm[bf], kg + off);
#pragma unroll
            for (int j = 0; j < 4; j++) cpasync16(vsm[bf][j], vg[j] + off);
        }
        CP_COMMIT();
        CP_WAIT1();             // tile t resident
        __syncthreads();

        const int bf = t & 1;
#pragma unroll 4
        for (int s = 0; s < 32; s++) {
            const ulonglong2* kp = (const ulonglong2*)&Ks[bf][s][0];
            ulonglong2 k01 = kp[0], k23 = kp[1], k45 = kp[2], k67 = kp[3];
            // split chains: 2 per query, interleaved for ILP
            ull da0 = 0ULL, da1 = 0ULL, db0 = 0ULL, db1 = 0ULL;
            da0 = ffma2(q2a[0], k01.x, da0);  db0 = ffma2(q2b[0], k01.x, db0);
            da1 = ffma2(q2a[1], k01.y, da1);  db1 = ffma2(q2b[1], k01.y, db1);
            da0 = ffma2(q2a[2], k23.x, da0);  db0 = ffma2(q2b[2], k23.x, db0);
            da1 = ffma2(q2a[3], k23.y, da1);  db1 = ffma2(q2b[3], k23.y, db1);
            da0 = ffma2(q2a[4], k45.x, da0);  db0 = ffma2(q2b[4], k45.x, db0);
            da1 = ffma2(q2a[5], k45.y, da1);  db1 = ffma2(q2b[5], k45.y, db1);
            da0 = ffma2(q2a[6], k67.x, da0);  db0 = ffma2(q2b[6], k67.x, db0);
            da1 = ffma2(q2a[7], k67.y, da1);  db1 = ffma2(q2b[7], k67.y, db1);
            float2 ha = unpack2(add2(da0, da1));
            float2 hb = unpack2(add2(db0, db1));
            float pa = ex2(ha.x + ha.y);
            float pb = ex2(hb.x + hb.y);
            la += pa;  lb += pb;
            ull p2a = dup2(pa), p2b = dup2(pb);

            const ulonglong2* vp = (const ulonglong2*)&Vs[bf][s][0];
#pragma unroll
            for (int j = 0; j < 16; j++) {
                ulonglong2 vv = vp[j];
                acca[2 * j + 0] = ffma2(p2a, vv.x, acca[2 * j + 0]);
                acca[2 * j + 1] = ffma2(p2a, vv.y, acca[2 * j + 1]);
                accb[2 * j + 0] = ffma2(p2b, vv.x, accb[2 * j + 0]);
                accb[2 * j + 1] = ffma2(p2b, vv.y, accb[2 * j + 1]);
            }
        }
        __syncthreads();
    }

    float ra = 1.0f / la, rb = 1.0f / lb;
    // q0 -> qhi=0, q1=q0+512 -> qhi=1, both at column q0.
    float* zb = d_zbuf + (size_t)b * QL * COUT + (size_t)(h * 128) * COUT + q0;
#pragma unroll
    for (int j = 0; j < 32; j++) {
        float2 a = unpack2(acca[j]);
        float2 bv = unpack2(accb[j]);
        zb[(size_t)(4 * j + 0) * COUT] = a.x * ra;   // d=2j,   q0
        zb[(size_t)(4 * j + 1) * COUT] = bv.x * rb;  // d=2j,   q1
        zb[(size_t)(4 * j + 2) * COUT] = a.y * ra;   // d=2j+1, q0
        zb[(size_t)(4 * j + 3) * COUT] = bv.y * rb;  // d=2j+1, q1
    }
}

// ---------------------------------------------------------------------------
// Launch
// ---------------------------------------------------------------------------
extern "C" void kernel_launch(void* const* d_in, const int* in_sizes, int n_in,
                              void* d_out, int out_size) {
    const float* x    = (const float*)d_in[0];
    const float* Wkv  = (const float*)d_in[1];
    const float* bkv  = (const float*)d_in[2];
    const float* gkv  = (const float*)d_in[3];
    const float* bekv = (const float*)d_in[4];
    const float* mkv  = (const float*)d_in[5];
    const float* vkv  = (const float*)d_in[6];
    const float* Wq   = (const float*)d_in[7];
    const float* bq   = (const float*)d_in[8];
    const float* gq   = (const float*)d_in[9];
    const float* beq  = (const float*)d_in[10];
    const float* mq   = (const float*)d_in[11];
    const float* vq   = (const float*)d_in[12];
    const float* Wp   = (const float*)d_in[13];
    const float* bp   = (const float*)d_in[14];
    const float* gp   = (const float*)d_in[15];
    const float* bep  = (const float*)d_in[16];
    const float* mp   = (const float*)d_in[17];
    const float* vp   = (const float*)d_in[18];
    float* out = (float*)d_out;

    fold_kernel<0><<<(CIN * KVD + 255) / 256, 256>>>(Wkv, bkv, gkv, bekv, mkv, vkv, CIN, KVD);
    fold_kernel<1><<<(CIN * QD + 255) / 256, 256>>>(Wq, bq, gq, beq, mq, vq, CIN, QD);
    fold_kernel<2><<<(COUT * COUT + 255) / 256, 256>>>(Wp, bp, gp, bep, mp, vp, COUT, COUT);

    // kv = BN(x @ Wkv + b):  [32768,256]x[256,640]
    gemm_kernel<0><<<dim3(KVD / 128, (BB * SEQL) / 128), 256>>>(x, nullptr, BB * SEQL, KVD, CIN);
    // q  = BN(xq @ Wq + b):  [8192,256]x[256,128] (strided row gather)
    gemm_kernel<1><<<dim3(QD / 128, (BB * QL) / 128), 256>>>(x, nullptr, BB * QL, QD, CIN);
    // fused flash attention -> d_zbuf (TF-reshaped), 2 queries/thread
    attn_kernel<<<dim3(4, HH, BB), 128>>>();
    // out = BN(hardswish(Z) @ Wp + b): [8192,512]x[512,512]
    gemm_kernel<2><<<dim3(COUT / 128, (BB * QL) / 128), 256>>>(nullptr, out, BB * QL, COUT, COUT);
}

// round 6
// speedup vs baseline: 3.6978x; 2.2651x over previous
#include <cuda_runtime.h>
#include <math.h>
#include <stdint.h>

// Problem constants
#define BB   8
#define SEQL 4096
#define QL   1024
#define CIN  256
#define KVD  640
#define QD   128
#define HH   8
#define KD   16
#define VD   64
#define COUT 512
#define EPSB 1e-3f

typedef unsigned long long ull;

// Intermediates as __device__ globals (no dynamic allocation allowed)
__device__ float d_kvbuf[BB * SEQL * KVD];   // [B, SEQ, 640]  (BN folded)
__device__ float d_qbuf [BB * QL * QD];      // [B, QLEN, 128] (BN folded)
__device__ float d_zbuf [BB * QL * COUT];    // [B, 1024, 512] attention out, TF-reshaped
__device__ float d_Wkvf[CIN * KVD];
__device__ float d_bkvf[KVD];
__device__ float d_Wqf [CIN * QD];
__device__ float d_bqf [QD];
__device__ float d_Wpf [COUT * COUT];
__device__ float d_bpf [COUT];

// ---- packed f32x2 helpers (sm_103a FFMA2 — only reachable via PTX) ----
__device__ __forceinline__ ull ffma2(ull a, ull b, ull c) {
    ull d;
    asm("fma.rn.f32x2 %0, %1, %2, %3;" : "=l"(d) : "l"(a), "l"(b), "l"(c));
    return d;
}
__device__ __forceinline__ ull dup2(float x) {
    ull d;
    asm("mov.b64 %0, {%1, %1};" : "=l"(d) : "f"(x));
    return d;
}
__device__ __forceinline__ float2 unpack2(ull v) {
    float2 r;
    asm("mov.b64 {%0, %1}, %2;" : "=f"(r.x), "=f"(r.y) : "l"(v));
    return r;
}
__device__ __forceinline__ float ex2(float x) {
    float y;
    asm("ex2.approx.ftz.f32 %0, %1;" : "=f"(y) : "f"(x));
    return y;
}
__device__ __forceinline__ uint32_t s2u(const void* p) {
    return (uint32_t)__cvta_generic_to_shared(p);
}
__device__ __forceinline__ void cpasync16(uint32_t dst, const void* src) {
    asm volatile("cp.async.cg.shared.global [%0], [%1], 16;" :: "r"(dst), "l"(src));
}
#define CP_COMMIT() asm volatile("cp.async.commit_group;")
#define CP_WAIT1()  asm volatile("cp.async.wait_group 1;")

// tf32 round-to-nearest conversion (f32 bit pattern, low 13 bits zero)
__device__ __forceinline__ uint32_t f2tf32(float x) {
    uint32_t r;
    asm("cvt.rna.tf32.f32 %0, %1;" : "=r"(r) : "f"(x));
    return r;
}
// m16n8k8 tf32 MMA, D = A*B + D
__device__ __forceinline__ void mma_tf32(float& c0, float& c1, float& c2, float& c3,
                                         uint32_t a0, uint32_t a1, uint32_t a2, uint32_t a3,
                                         uint32_t b0, uint32_t b1) {
    asm volatile("mma.sync.aligned.m16n8k8.row.col.f32.tf32.tf32.f32 "
                 "{%0,%1,%2,%3}, {%4,%5,%6,%7}, {%8,%9}, {%0,%1,%2,%3};"
                 : "+f"(c0), "+f"(c1), "+f"(c2), "+f"(c3)
                 : "r"(a0), "r"(a1), "r"(a2), "r"(a3), "r"(b0), "r"(b1));
}

__device__ __forceinline__ float hswish(float x) {
    return x * __saturatef(x * (1.0f / 6.0f) + 0.5f);
}

// ---------------------------------------------------------------------------
// Fold BN into weights + bias.
// ---------------------------------------------------------------------------
template <int WHICH>
__global__ void fold_kernel(const float* __restrict__ W, const float* __restrict__ b,
                            const float* __restrict__ gam, const float* __restrict__ bet,
                            const float* __restrict__ mu, const float* __restrict__ var,
                            int K, int N) {
    float* Wf; float* bf;
    if (WHICH == 0)      { Wf = d_Wkvf; bf = d_bkvf; }
    else if (WHICH == 1) { Wf = d_Wqf;  bf = d_bqf;  }
    else                 { Wf = d_Wpf;  bf = d_bpf;  }
    int i = blockIdx.x * 256 + threadIdx.x;
    if (i < K * N) {
        int n = i % N;
        float s = gam[n] * rsqrtf(var[n] + EPSB);
        Wf[i] = W[i] * s;
    }
    if (i < N) {
        float s = gam[i] * rsqrtf(var[i] + EPSB);
        bf[i] = (b[i] - mu[i]) * s + bet[i];
    }
}

// ---------------------------------------------------------------------------
// Tiled SGEMM, packed FFMA2 (unchanged from R5).
// ---------------------------------------------------------------------------
template <int MODE>
__global__ __launch_bounds__(256) void gemm_kernel(const float* __restrict__ Ain,
                                                   float* __restrict__ Cout,
                                                   int M, int N, int K) {
    const float* W;  const float* bias;  float* C;  const float* A = Ain;
    if (MODE == 0)      { W = d_Wkvf; bias = d_bkvf; C = d_kvbuf; }
    else if (MODE == 1) { W = d_Wqf;  bias = d_bqf;  C = d_qbuf;  }
    else                { W = d_Wpf;  bias = d_bpf;  C = Cout; A = d_zbuf; }

    __shared__ __align__(16) float As[16][132];
    __shared__ __align__(16) float Bs[16][128];

    int tid  = threadIdx.x;
    int row0 = blockIdx.y * 128;
    int col0 = blockIdx.x * 128;
    int ty = tid >> 5;
    int tx = tid & 31;

    ull acc2[8][4] = {};

    int lrow[2], lc4[2];
    const float* aptr[2];
#pragma unroll
    for (int j = 0; j < 2; j++) {
        int idx = tid + j * 256;
        int r = idx >> 2, c4 = idx & 3;
        lrow[j] = r; lc4[j] = c4;
        int gr = row0 + r;
        int src;
        if (MODE == 1) {
            int bb = gr >> 10, ql = gr & 1023;
            int qy = ql >> 5, qx = ql & 31;
            src = (bb << 12) + (qy << 7) + (qx << 1);
        } else {
            src = gr;
        }
        aptr[j] = A + (size_t)src * K + c4 * 4;
    }
    int br_[2], bc_[2];
#pragma unroll
    for (int j = 0; j < 2; j++) {
        int idx = tid + j * 256;
        br_[j] = idx >> 5; bc_[j] = (idx & 31) * 4;
    }

    for (int k0 = 0; k0 < K; k0 += 16) {
#pragma unroll
        for (int j = 0; j < 2; j++) {
            float4 a = *(const float4*)(aptr[j] + k0);
            if (MODE == 2) { a.x = hswish(a.x); a.y = hswish(a.y); a.z = hswish(a.z); a.w = hswish(a.w); }
            As[lc4[j] * 4 + 0][lrow[j]] = a.x;
            As[lc4[j] * 4 + 1][lrow[j]] = a.y;
            As[lc4[j] * 4 + 2][lrow[j]] = a.z;
            As[lc4[j] * 4 + 3][lrow[j]] = a.w;
        }
#pragma unroll
        for (int j = 0; j < 2; j++) {
            *(float4*)&Bs[br_[j]][bc_[j]] =
                *(const float4*)(W + (size_t)(k0 + br_[j]) * N + col0 + bc_[j]);
        }
        __syncthreads();
#pragma unroll
        for (int k = 0; k < 16; k++) {
            ull a2[8];
            {
                ulonglong2 p0 = *(ulonglong2*)&As[k][ty * 16];
                ulonglong2 p1 = *(ulonglong2*)&As[k][ty * 16 + 4];
                ulonglong2 p2 = *(ulonglong2*)&As[k][ty * 16 + 8];
                ulonglong2 p3 = *(ulonglong2*)&As[k][ty * 16 + 12];
                a2[0] = p0.x; a2[1] = p0.y; a2[2] = p1.x; a2[3] = p1.y;
                a2[4] = p2.x; a2[5] = p2.y; a2[6] = p3.x; a2[7] = p3.y;
            }
            float4 bv = *(float4*)&Bs[k][tx * 4];
            ull b2[4] = {dup2(bv.x), dup2(bv.y), dup2(bv.z), dup2(bv.w)};
#pragma unroll
            for (int i = 0; i < 8; i++)
#pragma unroll
                for (int j = 0; j < 4; j++)
                    acc2[i][j] = ffma2(a2[i], b2[j], acc2[i][j]);
        }
        __syncthreads();
    }

    float4 bv = *(const float4*)(bias + col0 + tx * 4);
    float bb4[4] = {bv.x, bv.y, bv.z, bv.w};
#pragma unroll
    for (int i = 0; i < 8; i++) {
        float r0[4], r1[4];
#pragma unroll
        for (int j = 0; j < 4; j++) {
            float2 c = unpack2(acc2[i][j]);
            r0[j] = c.x + bb4[j];
            r1[j] = c.y + bb4[j];
        }
        int gr = row0 + ty * 16 + 2 * i;
        float* p0 = C + (size_t)gr * N + col0 + tx * 4;
        *(float4*)p0       = *(float4*)&r0[0];
        *(float4*)(p0 + N) = *(float4*)&r1[0];
    }
}

// ---------------------------------------------------------------------------
// Flash attention via tf32 mma.sync (m16n8k8).
// Block = (b, h, 64 queries): 4 warps x 16 queries. Key tiles of 32,
// cp.async double-buffered. No online max; softmax in base 2.
//
// Per 8-key group / warp:
//   S[16,8] = Q[16,16] @ K^T       -> 2 mmas
//   P = exp2(S), tf32-masked; l accumulated per-thread, quad-reduced at end
//   O[16,64] += P[16,8] @ V[8,64]  -> 8 mmas; V rows permuted [0,2,4,6,1,3,5,7]
//     so the S accumulator fragment (c0,c2,c1,c3) is directly the A fragment.
//
// Smem: K [32][20] (conflict-free frag loads: (20g+t) spans all banks),
//       V [32][68] ((136t+g) mod 32 = 8t+g, all 32 lanes distinct).
// Output pre-reshaped: Z[b][h*128 + 2d + (q>>9)][q&511] = av[b,h,q,d]
// ---------------------------------------------------------------------------
__global__ __launch_bounds__(128) void attn_kernel() {
    __shared__ __align__(16) float Ks[2][32][20];
    __shared__ __align__(16) float Vs[2][32][68];

    int tid = threadIdx.x;
    int b = blockIdx.z, h = blockIdx.y;
    int q0 = blockIdx.x * 64;
    int w = tid >> 5;
    int lane = tid & 31;
    int g = lane >> 2, tg = lane & 3;

    const float* kvbase = d_kvbuf + (size_t)b * SEQL * KVD + h * 80;

    // --- cp.async tile-load assignments (16B each) ---
    int kr = tid >> 2, kc = (tid & 3) * 4;                  // K: 1 chunk/thread
    const float* kgp_ = kvbase + (size_t)kr * KVD + kc;
    uint32_t ksm[2] = { s2u(&Ks[0][kr][kc]), s2u(&Ks[1][kr][kc]) };
    const float* vgp_[4];
    uint32_t vsm[2][4];
#pragma unroll
    for (int j = 0; j < 4; j++) {
        int idx = tid + j * 128;
        int r = idx >> 4, c = (idx & 15) * 4;
        vgp_[j] = kvbase + (size_t)r * KVD + 16 + c;
        vsm[0][j] = s2u(&Vs[0][r][c]);
        vsm[1][j] = s2u(&Vs[1][r][c]);
    }

    // --- Q fragments: 2 k8-frags, rows (g, g+8), pre-scaled, tf32 ---
    const float SC = 0.25f * 1.44269504088896340736f;
    int qA = q0 + w * 16 + g;          // row g query
    int qB = qA + 8;                   // row g+8 query
    const float* qp0 = d_qbuf + (size_t)(b * QL + qA) * QD + h * KD;
    const float* qp1 = d_qbuf + (size_t)(b * QL + qB) * QD + h * KD;
    uint32_t qa[2][4];
#pragma unroll
    for (int f = 0; f < 2; f++) {
        qa[f][0] = f2tf32(qp0[f * 8 + tg] * SC);
        qa[f][1] = f2tf32(qp1[f * 8 + tg] * SC);
        qa[f][2] = f2tf32(qp0[f * 8 + tg + 4] * SC);
        qa[f][3] = f2tf32(qp1[f * 8 + tg + 4] * SC);
    }

    float acc[8][4];
#pragma unroll
    for (int i = 0; i < 8; i++)
#pragma unroll
        for (int j = 0; j < 4; j++) acc[i][j] = 0.0f;
    float l0 = 0.0f, l1 = 0.0f;

    // prefetch tile 0
    cpasync16(ksm[0], kgp_);
#pragma unroll
    for (int j = 0; j < 4; j++) cpasync16(vsm[0][j], vgp_[j]);
    CP_COMMIT();

    const int NT = SEQL / 32;
    for (int t = 0; t < NT; ++t) {
        if (t + 1 < NT) {
            size_t off = (size_t)(t + 1) * 32 * KVD;
            int nbf = (t + 1) & 1;
            cpasync16(ksm[nbf], kgp_ + off);
#pragma unroll
            for (int j = 0; j < 4; j++) cpasync16(vsm[nbf][j], vgp_[j] + off);
        }
        CP_COMMIT();
        CP_WAIT1();
        __syncthreads();

        const int bf = t & 1;
#pragma unroll
        for (int kg = 0; kg < 4; kg++) {
            const int krow = kg * 8;
            // K fragments: b0=(dim tg, key g), b1=(dim tg+4, key g); frag1 dims+8
            const float* krp = &Ks[bf][krow + g][0];
            uint32_t kb00 = __float_as_uint(krp[tg]);
            uint32_t kb01 = __float_as_uint(krp[tg + 4]);
            uint32_t kb10 = __float_as_uint(krp[tg + 8]);
            uint32_t kb11 = __float_as_uint(krp[tg + 12]);

            float c0 = 0.f, c1 = 0.f, c2 = 0.f, c3 = 0.f;
            mma_tf32(c0, c1, c2, c3, qa[0][0], qa[0][1], qa[0][2], qa[0][3], kb00, kb01);
            mma_tf32(c0, c1, c2, c3, qa[1][0], qa[1][1], qa[1][2], qa[1][3], kb10, kb11);

            // softmax weights, masked to tf32 bits so l matches the mma exactly
            uint32_t u0 = __float_as_uint(ex2(c0)) & 0xFFFFE000u;
            uint32_t u1 = __float_as_uint(ex2(c1)) & 0xFFFFE000u;
            uint32_t u2 = __float_as_uint(ex2(c2)) & 0xFFFFE000u;
            uint32_t u3 = __float_as_uint(ex2(c3)) & 0xFFFFE000u;
            l0 += __uint_as_float(u0) + __uint_as_float(u1);
            l1 += __uint_as_float(u2) + __uint_as_float(u3);

            // P as A-fragment: a0=c0, a1=c2, a2=c1, a3=c3 (keys [0,2,4,6,1,3,5,7])
            const float* vr0 = &Vs[bf][krow + 2 * tg][0];       // key 2tg
            const float* vr1 = &Vs[bf][krow + 2 * tg + 1][0];   // key 2tg+1
#pragma unroll
            for (int nt = 0; nt < 8; nt++) {
                uint32_t vb0 = __float_as_uint(vr0[8 * nt + g]);
                uint32_t vb1 = __float_as_uint(vr1[8 * nt + g]);
                mma_tf32(acc[nt][0], acc[nt][1], acc[nt][2], acc[nt][3],
                         u0, u2, u1, u3, vb0, vb1);
            }
        }
        __syncthreads();
    }

    // row-sum reduce across the quad (each thread held 2 of 8 cols per group)
    l0 += __shfl_xor_sync(0xffffffffu, l0, 1);
    l0 += __shfl_xor_sync(0xffffffffu, l0, 2);
    l1 += __shfl_xor_sync(0xffffffffu, l1, 1);
    l1 += __shfl_xor_sync(0xffffffffu, l1, 2);
    float r0 = 1.0f / l0, r1 = 1.0f / l1;

    float* zb = d_zbuf + (size_t)b * QL * COUT;
    int colA = qA & 511, hiA = qA >> 9;
    int colB = qB & 511, hiB = qB >> 9;
#pragma unroll
    for (int nt = 0; nt < 8; nt++) {
#pragma unroll
        for (int e = 0; e < 2; e++) {
            int d = 8 * nt + 2 * tg + e;
            zb[(size_t)(h * 128 + 2 * d + hiA) * COUT + colA] = acc[nt][e] * r0;
            zb[(size_t)(h * 128 + 2 * d + hiB) * COUT + colB] = acc[nt][2 + e] * r1;
        }
    }
}

// ---------------------------------------------------------------------------
// Launch
// ---------------------------------------------------------------------------
extern "C" void kernel_launch(void* const* d_in, const int* in_sizes, int n_in,
                              void* d_out, int out_size) {
    const float* x    = (const float*)d_in[0];
    const float* Wkv  = (const float*)d_in[1];
    const float* bkv  = (const float*)d_in[2];
    const float* gkv  = (const float*)d_in[3];
    const float* bekv = (const float*)d_in[4];
    const float* mkv  = (const float*)d_in[5];
    const float* vkv  = (const float*)d_in[6];
    const float* Wq   = (const float*)d_in[7];
    const float* bq   = (const float*)d_in[8];
    const float* gq   = (const float*)d_in[9];
    const float* beq  = (const float*)d_in[10];
    const float* mq   = (const float*)d_in[11];
    const float* vq   = (const float*)d_in[12];
    const float* Wp   = (const float*)d_in[13];
    const float* bp   = (const float*)d_in[14];
    const float* gp   = (const float*)d_in[15];
    const float* bep  = (const float*)d_in[16];
    const float* mp   = (const float*)d_in[17];
    const float* vp   = (const float*)d_in[18];
    float* out = (float*)d_out;

    fold_kernel<0><<<(CIN * KVD + 255) / 256, 256>>>(Wkv, bkv, gkv, bekv, mkv, vkv, CIN, KVD);
    fold_kernel<1><<<(CIN * QD + 255) / 256, 256>>>(Wq, bq, gq, beq, mq, vq, CIN, QD);
    fold_kernel<2><<<(COUT * COUT + 255) / 256, 256>>>(Wp, bp, gp, bep, mp, vp, COUT, COUT);

    // kv = BN(x @ Wkv + b):  [32768,256]x[256,640]
    gemm_kernel<0><<<dim3(KVD / 128, (BB * SEQL) / 128), 256>>>(x, nullptr, BB * SEQL, KVD, CIN);
    // q  = BN(xq @ Wq + b):  [8192,256]x[256,128] (strided row gather)
    gemm_kernel<1><<<dim3(QD / 128, (BB * QL) / 128), 256>>>(x, nullptr, BB * QL, QD, CIN);
    // fused flash attention (tf32 mma) -> d_zbuf (TF-reshaped)
    attn_kernel<<<dim3(QL / 64, HH, BB), 128>>>();
    // out = BN(hardswish(Z) @ Wp + b): [8192,512]x[512,512]
    gemm_kernel<2><<<dim3(COUT / 128, (BB * QL) / 128), 256>>>(nullptr, out, BB * QL, COUT, COUT);
}

// round 8
// speedup vs baseline: 4.2865x; 1.1592x over previous
#include <cuda_runtime.h>
#include <math.h>
#include <stdint.h>

// Problem constants
#define BB   8
#define SEQL 4096
#define QL   1024
#define CIN  256
#define KVD  640
#define QD   128
#define HH   8
#define KD   16
#define VD   64
#define COUT 512
#define EPSB 1e-3f

typedef unsigned long long ull;

// Intermediates as __device__ globals (no dynamic allocation allowed)
__device__ float d_kvbuf[BB * SEQL * KVD];   // [B, SEQ, 640]  (BN folded)
__device__ float d_qbuf [BB * QL * QD];      // [B, QLEN, 128] (BN folded)
__device__ float d_zbuf [BB * QL * COUT];    // [B, 1024, 512] attention out, TF-reshaped
__device__ float d_Wkvf[CIN * KVD];
__device__ float d_bkvf[KVD];
__device__ float d_Wqf [CIN * QD];
__device__ float d_bqf [QD];
__device__ float d_Wpf [COUT * COUT];
__device__ float d_bpf [COUT];

__device__ __forceinline__ float ex2(float x) {
    float y;
    asm("ex2.approx.ftz.f32 %0, %1;" : "=f"(y) : "f"(x));
    return y;
}
__device__ __forceinline__ uint32_t s2u(const void* p) {
    return (uint32_t)__cvta_generic_to_shared(p);
}
__device__ __forceinline__ void cpasync16(uint32_t dst, const void* src) {
    asm volatile("cp.async.cg.shared.global [%0], [%1], 16;" :: "r"(dst), "l"(src));
}
#define CP_COMMIT() asm volatile("cp.async.commit_group;")
#define CP_WAIT1()  asm volatile("cp.async.wait_group 1;")

// tf32 round-to-nearest conversion (f32 bit pattern, low 13 bits zero)
__device__ __forceinline__ uint32_t f2tf32(float x) {
    uint32_t r;
    asm("cvt.rna.tf32.f32 %0, %1;" : "=r"(r) : "f"(x));
    return r;
}
__device__ __forceinline__ float tf32r(float x) {
    return __uint_as_float(f2tf32(x));
}
// m16n8k8 tf32 MMA, D = A*B + D
__device__ __forceinline__ void mma_tf32(float& c0, float& c1, float& c2, float& c3,
                                         uint32_t a0, uint32_t a1, uint32_t a2, uint32_t a3,
                                         uint32_t b0, uint32_t b1) {
    asm volatile("mma.sync.aligned.m16n8k8.row.col.f32.tf32.tf32.f32 "
                 "{%0,%1,%2,%3}, {%4,%5,%6,%7}, {%8,%9}, {%0,%1,%2,%3};"
                 : "+f"(c0), "+f"(c1), "+f"(c2), "+f"(c3)
                 : "r"(a0), "r"(a1), "r"(a2), "r"(a3), "r"(b0), "r"(b1));
}

__device__ __forceinline__ float hswish(float x) {
    return x * __saturatef(x * (1.0f / 6.0f) + 0.5f);
}

// ---------------------------------------------------------------------------
// Fold BN into weights + bias.
// ---------------------------------------------------------------------------
template <int WHICH>
__global__ void fold_kernel(const float* __restrict__ W, const float* __restrict__ b,
                            const float* __restrict__ gam, const float* __restrict__ bet,
                            const float* __restrict__ mu, const float* __restrict__ var,
                            int K, int N) {
    float* Wf; float* bf;
    if (WHICH == 0)      { Wf = d_Wkvf; bf = d_bkvf; }
    else if (WHICH == 1) { Wf = d_Wqf;  bf = d_bqf;  }
    else                 { Wf = d_Wpf;  bf = d_bpf;  }
    int i = blockIdx.x * 256 + threadIdx.x;
    if (i < K * N) {
        int n = i % N;
        float s = gam[n] * rsqrtf(var[n] + EPSB);
        Wf[i] = W[i] * s;
    }
    if (i < N) {
        float s = gam[i] * rsqrtf(var[i] + EPSB);
        bf[i] = (b[i] - mu[i]) * s + bet[i];
    }
}

// ---------------------------------------------------------------------------
// tf32 tensor-core GEMM: C[M,N] = f(A[M,K]) @ W[K,N] + bias
// BM=128, BN=128, BK=16, 256 threads (8 warps as 4m x 2n, warp tile 32x64).
// A and W rounded to tf32 (rna) on smem store; both stored [k][*] (132-padded)
// so all fragment LDS are conflict-free (addr mod 32 = 4*tg + g pattern).
// THREE=1: 3xTF32 (hi/lo split, hi*hi + hi*lo + lo*hi) for fp32-grade accuracy.
// MODE 0: kv (A=x), 1: q (A=x strided gather), 2: proj (A=hswish(zbuf)).
// ---------------------------------------------------------------------------
template <int MODE, int THREE>
__global__ __launch_bounds__(256) void tgemm_kernel(const float* __restrict__ Ain,
                                                    float* __restrict__ Cout,
                                                    int M, int N, int K) {
    const float* W;  const float* bias;  float* C;  const float* A = Ain;
    if (MODE == 0)      { W = d_Wkvf; bias = d_bkvf; C = d_kvbuf; }
    else if (MODE == 1) { W = d_Wqf;  bias = d_bqf;  C = d_qbuf;  }
    else                { W = d_Wpf;  bias = d_bpf;  C = Cout; A = d_zbuf; }

    __shared__ __align__(16) float Ah[16][132];
    __shared__ __align__(16) float Bh[16][132];
    __shared__ __align__(16) float Al[THREE ? 16 : 1][THREE ? 132 : 4];
    __shared__ __align__(16) float Bl[THREE ? 16 : 1][THREE ? 132 : 4];

    int tid  = threadIdx.x;
    int m0 = blockIdx.y * 128;
    int n0 = blockIdx.x * 128;
    int w = tid >> 5, lane = tid & 31;
    int g = lane >> 2, tg = lane & 3;
    int wm = w >> 1, wn = w & 1;           // warp tile: rows wm*32+, cols wn*64+

    float acc[2][8][4];
#pragma unroll
    for (int i = 0; i < 2; i++)
#pragma unroll
        for (int j = 0; j < 8; j++)
#pragma unroll
            for (int e = 0; e < 4; e++) acc[i][j][e] = 0.0f;

    // A-load assignment: 2 float4 per thread (128 rows x 16 cols)
    int lrow[2], lc4[2];
    const float* aptr[2];
#pragma unroll
    for (int j = 0; j < 2; j++) {
        int idx = tid + j * 256;
        int r = idx >> 2, c4 = idx & 3;
        lrow[j] = r; lc4[j] = c4;
        int gr = m0 + r;
        int src;
        if (MODE == 1) {
            int bb = gr >> 10, ql = gr & 1023;
            int qy = ql >> 5, qx = ql & 31;
            src = (bb << 12) + (qy << 7) + (qx << 1);
        } else {
            src = gr;
        }
        aptr[j] = A + (size_t)src * K + c4 * 4;
    }
    // B-load: 2 float4 per thread (16 rows x 128 cols)
    int bkr[2], bnc[2];
#pragma unroll
    for (int j = 0; j < 2; j++) {
        int idx = tid + j * 256;
        bkr[j] = idx >> 5; bnc[j] = (idx & 31) * 4;
    }

    for (int k0 = 0; k0 < K; k0 += 16) {
        // --- A tile -> smem (transposed to [k][m]), tf32-rounded (+lo) ---
#pragma unroll
        for (int j = 0; j < 2; j++) {
            float4 a = *(const float4*)(aptr[j] + k0);
            if (MODE == 2) { a.x = hswish(a.x); a.y = hswish(a.y); a.z = hswish(a.z); a.w = hswish(a.w); }
            float av[4] = {a.x, a.y, a.z, a.w};
#pragma unroll
            for (int e = 0; e < 4; e++) {
                float h = tf32r(av[e]);
                Ah[lc4[j] * 4 + e][lrow[j]] = h;
                if (THREE) Al[lc4[j] * 4 + e][lrow[j]] = av[e] - h;
            }
        }
        // --- B tile -> smem [k][n], tf32-rounded (+lo), float4 stores ---
#pragma unroll
        for (int j = 0; j < 2; j++) {
            float4 b = *(const float4*)(W + (size_t)(k0 + bkr[j]) * N + n0 + bnc[j]);
            float4 h = {tf32r(b.x), tf32r(b.y), tf32r(b.z), tf32r(b.w)};
            *(float4*)&Bh[bkr[j]][bnc[j]] = h;
            if (THREE) {
                float4 lo = {b.x - h.x, b.y - h.y, b.z - h.z, b.w - h.w};
                *(float4*)&Bl[bkr[j]][bnc[j]] = lo;
            }
        }
        __syncthreads();

#pragma unroll
        for (int k8 = 0; k8 < 16; k8 += 8) {
            uint32_t ah[2][4], al[2][4];
#pragma unroll
            for (int mi = 0; mi < 2; mi++) {
                int r = wm * 32 + mi * 16 + g;
                ah[mi][0] = __float_as_uint(Ah[k8 + tg][r]);
                ah[mi][1] = __float_as_uint(Ah[k8 + tg][r + 8]);
                ah[mi][2] = __float_as_uint(Ah[k8 + tg + 4][r]);
                ah[mi][3] = __float_as_uint(Ah[k8 + tg + 4][r + 8]);
                if (THREE) {
                    al[mi][0] = __float_as_uint(Al[k8 + tg][r]);
                    al[mi][1] = __float_as_uint(Al[k8 + tg][r + 8]);
                    al[mi][2] = __float_as_uint(Al[k8 + tg + 4][r]);
                    al[mi][3] = __float_as_uint(Al[k8 + tg + 4][r + 8]);
                }
            }
#pragma unroll
            for (int nj = 0; nj < 8; nj++) {
                int n = wn * 64 + nj * 8 + g;
                uint32_t bh0 = __float_as_uint(Bh[k8 + tg][n]);
                uint32_t bh1 = __float_as_uint(Bh[k8 + tg + 4][n]);
#pragma unroll
                for (int mi = 0; mi < 2; mi++)
                    mma_tf32(acc[mi][nj][0], acc[mi][nj][1], acc[mi][nj][2], acc[mi][nj][3],
                             ah[mi][0], ah[mi][1], ah[mi][2], ah[mi][3], bh0, bh1);
                if (THREE) {
                    uint32_t bl0 = __float_as_uint(Bl[k8 + tg][n]);
                    uint32_t bl1 = __float_as_uint(Bl[k8 + tg + 4][n]);
#pragma unroll
                    for (int mi = 0; mi < 2; mi++) {
                        mma_tf32(acc[mi][nj][0], acc[mi][nj][1], acc[mi][nj][2], acc[mi][nj][3],
                                 ah[mi][0], ah[mi][1], ah[mi][2], ah[mi][3], bl0, bl1);
                        mma_tf32(acc[mi][nj][0], acc[mi][nj][1], acc[mi][nj][2], acc[mi][nj][3],
                                 al[mi][0], al[mi][1], al[mi][2], al[mi][3], bh0, bh1);
                    }
                }
            }
        }
        __syncthreads();
    }

    // epilogue: thread (g,tg) holds rows (.. + g, + 8), cols (.. + 2tg, +1)
#pragma unroll
    for (int mi = 0; mi < 2; mi++) {
#pragma unroll
        for (int nj = 0; nj < 8; nj++) {
            int row = m0 + wm * 32 + mi * 16 + g;
            int col = n0 + wn * 64 + nj * 8 + 2 * tg;
            float b0 = bias[col], b1 = bias[col + 1];
            float2 v0 = {acc[mi][nj][0] + b0, acc[mi][nj][1] + b1};
            float2 v1 = {acc[mi][nj][2] + b0, acc[mi][nj][3] + b1};
            *(float2*)(C + (size_t)row * N + col) = v0;
            *(float2*)(C + (size_t)(row + 8) * N + col) = v1;
        }
    }
}

// ---------------------------------------------------------------------------
// Flash attention via tf32 mma.sync (m16n8k8) — unchanged from R6.
// ---------------------------------------------------------------------------
__global__ __launch_bounds__(128) void attn_kernel() {
    __shared__ __align__(16) float Ks[2][32][20];
    __shared__ __align__(16) float Vs[2][32][68];

    int tid = threadIdx.x;
    int b = blockIdx.z, h = blockIdx.y;
    int q0 = blockIdx.x * 64;
    int w = tid >> 5;
    int lane = tid & 31;
    int g = lane >> 2, tg = lane & 3;

    const float* kvbase = d_kvbuf + (size_t)b * SEQL * KVD + h * 80;

    int kr = tid >> 2, kc = (tid & 3) * 4;
    const float* kgp_ = kvbase + (size_t)kr * KVD + kc;
    uint32_t ksm[2] = { s2u(&Ks[0][kr][kc]), s2u(&Ks[1][kr][kc]) };
    const float* vgp_[4];
    uint32_t vsm[2][4];
#pragma unroll
    for (int j = 0; j < 4; j++) {
        int idx = tid + j * 128;
        int r = idx >> 4, c = (idx & 15) * 4;
        vgp_[j] = kvbase + (size_t)r * KVD + 16 + c;
        vsm[0][j] = s2u(&Vs[0][r][c]);
        vsm[1][j] = s2u(&Vs[1][r][c]);
    }

    const float SC = 0.25f * 1.44269504088896340736f;
    int qA = q0 + w * 16 + g;
    int qB = qA + 8;
    const float* qp0 = d_qbuf + (size_t)(b * QL + qA) * QD + h * KD;
    const float* qp1 = d_qbuf + (size_t)(b * QL + qB) * QD + h * KD;
    uint32_t qa[2][4];
#pragma unroll
    for (int f = 0; f < 2; f++) {
        qa[f][0] = f2tf32(qp0[f * 8 + tg] * SC);
        qa[f][1] = f2tf32(qp1[f * 8 + tg] * SC);
        qa[f][2] = f2tf32(qp0[f * 8 + tg + 4] * SC);
        qa[f][3] = f2tf32(qp1[f * 8 + tg + 4] * SC);
    }

    float acc[8][4];
#pragma unroll
    for (int i = 0; i < 8; i++)
#pragma unroll
        for (int j = 0; j < 4; j++) acc[i][j] = 0.0f;
    float l0 = 0.0f, l1 = 0.0f;

    cpasync16(ksm[0], kgp_);
#pragma unroll
    for (int j = 0; j < 4; j++) cpasync16(vsm[0][j], vgp_[j]);
    CP_COMMIT();

    const int NT = SEQL / 32;
    for (int t = 0; t < NT; ++t) {
        if (t + 1 < NT) {
            size_t off = (size_t)(t + 1) * 32 * KVD;
            int nbf = (t + 1) & 1;
            cpasync16(ksm[nbf], kgp_ + off);
#pragma unroll
            for (int j = 0; j < 4; j++) cpasync16(vsm[nbf][j], vgp_[j] + off);
        }
        CP_COMMIT();
        CP_WAIT1();
        __syncthreads();

        const int bf = t & 1;
#pragma unroll
        for (int kg = 0; kg < 4; kg++) {
            const int krow = kg * 8;
            const float* krp = &Ks[bf][krow + g][0];
            uint32_t kb00 = __float_as_uint(krp[tg]);
            uint32_t kb01 = __float_as_uint(krp[tg + 4]);
            uint32_t kb10 = __float_as_uint(krp[tg + 8]);
            uint32_t kb11 = __float_as_uint(krp[tg + 12]);

            float c0 = 0.f, c1 = 0.f, c2 = 0.f, c3 = 0.f;
            mma_tf32(c0, c1, c2, c3, qa[0][0], qa[0][1], qa[0][2], qa[0][3], kb00, kb01);
            mma_tf32(c0, c1, c2, c3, qa[1][0], qa[1][1], qa[1][2], qa[1][3], kb10, kb11);

            uint32_t u0 = __float_as_uint(ex2(c0)) & 0xFFFFE000u;
            uint32_t u1 = __float_as_uint(ex2(c1)) & 0xFFFFE000u;
            uint32_t u2 = __float_as_uint(ex2(c2)) & 0xFFFFE000u;
            uint32_t u3 = __float_as_uint(ex2(c3)) & 0xFFFFE000u;
            l0 += __uint_as_float(u0) + __uint_as_float(u1);
            l1 += __uint_as_float(u2) + __uint_as_float(u3);

            const float* vr0 = &Vs[bf][krow + 2 * tg][0];
            const float* vr1 = &Vs[bf][krow + 2 * tg + 1][0];
#pragma unroll
            for (int nt = 0; nt < 8; nt++) {
                uint32_t vb0 = __float_as_uint(vr0[8 * nt + g]);
                uint32_t vb1 = __float_as_uint(vr1[8 * nt + g]);
                mma_tf32(acc[nt][0], acc[nt][1], acc[nt][2], acc[nt][3],
                         u0, u2, u1, u3, vb0, vb1);
            }
        }
        __syncthreads();
    }

    l0 += __shfl_xor_sync(0xffffffffu, l0, 1);
    l0 += __shfl_xor_sync(0xffffffffu, l0, 2);
    l1 += __shfl_xor_sync(0xffffffffu, l1, 1);
    l1 += __shfl_xor_sync(0xffffffffu, l1, 2);
    float r0 = 1.0f / l0, r1 = 1.0f / l1;

    float* zb = d_zbuf + (size_t)b * QL * COUT;
    int colA = qA & 511, hiA = qA >> 9;
    int colB = qB & 511, hiB = qB >> 9;
#pragma unroll
    for (int nt = 0; nt < 8; nt++) {
#pragma unroll
        for (int e = 0; e < 2; e++) {
            int d = 8 * nt + 2 * tg + e;
            zb[(size_t)(h * 128 + 2 * d + hiA) * COUT + colA] = acc[nt][e] * r0;
            zb[(size_t)(h * 128 + 2 * d + hiB) * COUT + colB] = acc[nt][2 + e] * r1;
        }
    }
}

// ---------------------------------------------------------------------------
// Launch
// ---------------------------------------------------------------------------
extern "C" void kernel_launch(void* const* d_in, const int* in_sizes, int n_in,
                              void* d_out, int out_size) {
    const float* x    = (const float*)d_in[0];
    const float* Wkv  = (const float*)d_in[1];
    const float* bkv  = (const float*)d_in[2];
    const float* gkv  = (const float*)d_in[3];
    const float* bekv = (const float*)d_in[4];
    const float* mkv  = (const float*)d_in[5];
    const float* vkv  = (const float*)d_in[6];
    const float* Wq   = (const float*)d_in[7];
    const float* bq   = (const float*)d_in[8];
    const float* gq   = (const float*)d_in[9];
    const float* beq  = (const float*)d_in[10];
    const float* mq   = (const float*)d_in[11];
    const float* vq   = (const float*)d_in[12];
    const float* Wp   = (const float*)d_in[13];
    const float* bp   = (const float*)d_in[14];
    const float* gp   = (const float*)d_in[15];
    const float* bep  = (const float*)d_in[16];
    const float* mp   = (const float*)d_in[17];
    const float* vp   = (const float*)d_in[18];
    float* out = (float*)d_out;

    fold_kernel<0><<<(CIN * KVD + 255) / 256, 256>>>(Wkv, bkv, gkv, bekv, mkv, vkv, CIN, KVD);
    fold_kernel<1><<<(CIN * QD + 255) / 256, 256>>>(Wq, bq, gq, beq, mq, vq, CIN, QD);
    fold_kernel<2><<<(COUT * COUT + 255) / 256, 256>>>(Wp, bp, gp, bep, mp, vp, COUT, COUT);

    // kv = BN(x @ Wkv + b):  [32768,256]x[256,640], plain tf32
    tgemm_kernel<0, 0><<<dim3(KVD / 128, (BB * SEQL) / 128), 256>>>(x, nullptr, BB * SEQL, KVD, CIN);
    // q  = BN(xq @ Wq + b):  [8192,256]x[256,128], plain tf32
    tgemm_kernel<1, 0><<<dim3(QD / 128, (BB * QL) / 128), 256>>>(x, nullptr, BB * QL, QD, CIN);
    // fused flash attention (tf32 mma) -> d_zbuf (TF-reshaped)
    attn_kernel<<<dim3(QL / 64, HH, BB), 128>>>();
    // out = BN(hardswish(Z) @ Wp + b): [8192,512]x[512,512], 3xTF32
    tgemm_kernel<2, 1><<<dim3(COUT / 128, (BB * QL) / 128), 256>>>(nullptr, out, BB * QL, COUT, COUT);
}